// round 14
// baseline (speedup 1.0000x reference)
#include <cuda_runtime.h>
#include <cuda_fp16.h>
#include <stdint.h>

#define B_    32
#define CIN_  256
#define HW_   784
#define COUT_ 256

// ===========================================================================
// PTX helpers (arch-generic: ldmatrix + mma.sync, valid at sm_103 target)
// ===========================================================================
__device__ __forceinline__ uint32_t smem_to_u32(const void* p) {
    uint32_t a;
    asm("{ .reg .u64 t; cvta.to.shared.u64 t, %1; cvt.u32.u64 %0, t; }" : "=r"(a) : "l"(p));
    return a;
}
#define LDSM_X4(r0, r1, r2, r3, addr) \
    asm volatile("ldmatrix.sync.aligned.m8n8.x4.shared.b16 {%0,%1,%2,%3}, [%4];" \
        : "=r"(r0), "=r"(r1), "=r"(r2), "=r"(r3) : "r"(addr))
#define LDSM_X2(r0, r1, addr) \
    asm volatile("ldmatrix.sync.aligned.m8n8.x2.shared.b16 {%0,%1}, [%2];" \
        : "=r"(r0), "=r"(r1) : "r"(addr))
#define MMA_F16(d, a, bgg) \
    asm volatile("mma.sync.aligned.m16n8k16.row.col.f32.f16.f16.f32 " \
        "{%0,%1,%2,%3}, {%4,%5,%6,%7}, {%8,%9}, {%0,%1,%2,%3};" \
        : "+f"((d)[0]), "+f"((d)[1]), "+f"((d)[2]), "+f"((d)[3]) \
        : "r"((a)[0]), "r"((a)[1]), "r"((a)[2]), "r"((a)[3]), \
          "r"((bgg)[0]), "r"((bgg)[1]))

// ===========================================================================
// Scratch (__device__ globals; allocation-free rule)
// ===========================================================================
__device__ float    g_pooled[B_ * CIN_];
__device__ float    g_prob[B_ * 4 * COUT_];
__device__ uint32_t g_aggw_split[(size_t)B_ * COUT_ * 9 * CIN_];   // [b][o][tap][ci] (wh<<16|wl)
// A fragments: [b][ot(16)][tap(9)][cc(16)] -> 1KB block: 32 lanes x uint4 (wh), then (wl)
__device__ uint4    g_frag[(size_t)B_ * 16 * 9 * 16 * 64];

__device__ __forceinline__ uint32_t pack_split_h(float v) {
    __half h = __float2half_rn(v);
    float rem = v - __half2float(h);
    __half l = __float2half_rn(rem);
    return ((uint32_t)__half_as_ushort(h) << 16) | (uint32_t)__half_as_ushort(l);
}

// ---------------------------------------------------------------------------
// Kernel 0: pooling.  One warp per (b, channel).
// ---------------------------------------------------------------------------
__global__ void pool_kernel(const float* __restrict__ x) {
    int gw   = blockIdx.x * 8 + (threadIdx.x >> 5);
    int lane = threadIdx.x & 31;
    const float4* xp = (const float4*)(x + (size_t)gw * HW_);
    float s = 0.f;
    for (int i = lane; i < HW_ / 4; i += 32) {
        float4 v = xp[i];
        s += (v.x + v.y) + (v.z + v.w);
    }
    #pragma unroll
    for (int off = 16; off; off >>= 1) s += __shfl_xor_sync(0xffffffffu, s, off);
    if (lane == 0) g_pooled[gw] = s * (1.0f / 784.0f);
}

// ---------------------------------------------------------------------------
// Kernel 1: routing (fc1 + fc2 + softmax).
// ---------------------------------------------------------------------------
__global__ void routing_kernel(const float* __restrict__ fc1_w,
                               const float* __restrict__ fc2_w,
                               const float* __restrict__ fc2_b) {
    int b   = blockIdx.x;
    int tid = threadIdx.x;
    __shared__ float pooled[CIN_];
    __shared__ float hs[64];

    pooled[tid] = g_pooled[b * CIN_ + tid];
    __syncthreads();
    if (tid < 64) {
        const float* wr = fc1_w + (size_t)tid * CIN_;
        float acc = 0.f;
        #pragma unroll 8
        for (int c = 0; c < CIN_; ++c) acc += pooled[c] * wr[c];
        hs[tid] = fmaxf(acc, 0.f);
    }
    __syncthreads();
    int o = tid;
    float y[4];
    #pragma unroll
    for (int k = 0; k < 4; ++k) {
        int m = k * COUT_ + o;
        const float* wr = fc2_w + (size_t)m * 64;
        float acc = fc2_b[m];
        #pragma unroll 8
        for (int j = 0; j < 64; ++j) acc += hs[j] * wr[j];
        y[k] = acc * 0.125f;
    }
    float mx = fmaxf(fmaxf(y[0], y[1]), fmaxf(y[2], y[3]));
    float e[4], se = 0.f;
    #pragma unroll
    for (int k = 0; k < 4; ++k) { e[k] = expf(y[k] - mx); se += e[k]; }
    float inv = 1.0f / se;
    #pragma unroll
    for (int k = 0; k < 4; ++k)
        g_prob[((size_t)b * 4 + k) * COUT_ + o] = e[k] * inv;
}

// ---------------------------------------------------------------------------
// Kernel 2: aggregate + fp16-split + transpose.  Grid (o=256, bh=2).
// ---------------------------------------------------------------------------
__global__ void aggw_split_kernel(const float* __restrict__ weight) {
    __shared__ float s[4][2304];
    int o = blockIdx.x, bh = blockIdx.y, tid = threadIdx.x;

    #pragma unroll
    for (int k = 0; k < 4; ++k) {
        const float* wk = weight + ((size_t)(k * COUT_ + o)) * 2304;
        for (int j = tid; j < 2304; j += 256) s[k][j] = wk[j];
    }
    __syncthreads();

    for (int b = bh * 16; b < bh * 16 + 16; ++b) {
        float p0 = g_prob[((size_t)b * 4 + 0) * COUT_ + o];
        float p1 = g_prob[((size_t)b * 4 + 1) * COUT_ + o];
        float p2 = g_prob[((size_t)b * 4 + 2) * COUT_ + o];
        float p3 = g_prob[((size_t)b * 4 + 3) * COUT_ + o];
        uint32_t* dst = g_aggw_split + ((size_t)b * COUT_ + o) * 2304;
        for (int j = tid; j < 2304; j += 256) {
            int t = j >> 8, ci = j & 255;
            int idx = ci * 9 + t;
            dst[j] = pack_split_h(p0 * s[0][idx] + p1 * s[1][idx] +
                                  p2 * s[2][idx] + p3 * s[3][idx]);
        }
    }
}

// ---------------------------------------------------------------------------
// Kernel 2b: repack split weights into mma A-fragment order.
// grid (b=32, ot=16) x 256 thr.  Per fragment (t,cc): lane holds its
// m16n8k16 A fragment -> 4 LDG.64 in, 2 STG.128 out (coalesced 1KB blocks).
// ---------------------------------------------------------------------------
__global__ void repack_frag_kernel() {
    int b = blockIdx.x, ot = blockIdx.y;
    int warp = threadIdx.x >> 5, lane = threadIdx.x & 31;
    int r0 = lane >> 2, k = (lane & 3) * 2;

    for (int f = warp; f < 144; f += 8) {       // f = t*16 + cc
        int t = f >> 4, cc = f & 15;
        const uint32_t* src = g_aggw_split +
            (((size_t)(b * 256 + ot * 16)) * 9 + t) * 256 + cc * 16;
        const uint32_t* s0 = src + (size_t)r0 * 2304 + k;
        const uint32_t* s1 = src + (size_t)(r0 + 8) * 2304 + k;
        uint2 p00 = *(const uint2*)(s0);        // rows r0,   k..k+1
        uint2 p02 = *(const uint2*)(s0 + 8);    // rows r0,   k+8..k+9
        uint2 p10 = *(const uint2*)(s1);        // rows r0+8, k..k+1
        uint2 p12 = *(const uint2*)(s1 + 8);

        uint4 wh = make_uint4(__byte_perm(p00.x, p00.y, 0x7632),
                              __byte_perm(p10.x, p10.y, 0x7632),
                              __byte_perm(p02.x, p02.y, 0x7632),
                              __byte_perm(p12.x, p12.y, 0x7632));
        uint4 wl = make_uint4(__byte_perm(p00.x, p00.y, 0x5410),
                              __byte_perm(p10.x, p10.y, 0x5410),
                              __byte_perm(p02.x, p02.y, 0x5410),
                              __byte_perm(p12.x, p12.y, 0x5410));
        size_t frag = (((size_t)(b * 16 + ot)) * 9 + t) * 16 + cc;
        uint4* dst = g_frag + frag * 64;
        dst[lane]      = wh;
        dst[32 + lane] = wl;
    }
}

// ---------------------------------------------------------------------------
// Kernel 3: conv.  A fragments straight from gmem (LDG.128, prefetch 1 tap),
// B from transposed slab via ldmatrix (built once per ci-chunk).
// Only 2 barriers per ci-chunk.  CTA: 128 outs x 112 px, 8 warps 4(M)x2(N).
// ---------------------------------------------------------------------------
__global__ __launch_bounds__(256, 2)
void conv_mma_kernel(const float* __restrict__ x, float* __restrict__ out) {
    __shared__ __align__(16) char slabT[180 * 48];       // [spatial][16 ci] fp16

    uint32_t sT = smem_to_u32(slabT);
    int tid = threadIdx.x, lane = tid & 31, wid = tid >> 5;
    int b = blockIdx.z, o0 = blockIdx.y * 128, r0 = blockIdx.x * 4;
    int wm = wid & 3, wn = wid >> 2;
    int otb = blockIdx.y * 8 + wm * 2;                   // o-tile base for this warp

    float d[2][7][4];
    #pragma unroll
    for (int mt = 0; mt < 2; ++mt)
        #pragma unroll
        for (int nt = 0; nt < 7; ++nt)
            #pragma unroll
            for (int j = 0; j < 4; ++j) d[mt][nt][j] = 0.f;

    // B ldmatrix lane addresses (tap adds a constant offset)
    int lb_row  = (lane & 7) + (lane >> 4) * 8;
    int lb_kb   = ((lane >> 3) & 1) * 16;
    int lb2_row = lane & 7;
    int lb2_kb  = ((lane >> 3) & 1) * 16;
    uint32_t addrB[4];
    #pragma unroll
    for (int np = 0; np < 3; ++np) {
        int n = wn * 56 + np * 16 + lb_row;
        int rl = n / 28, c = n - rl * 28;
        addrB[np] = sT + (uint32_t)(rl * 30 + c) * 48 + lb_kb;
    }
    {
        int n = wn * 56 + 48 + lb2_row;
        int rl = n / 28, c = n - rl * 28;
        addrB[3] = sT + (uint32_t)(rl * 30 + c) * 48 + lb2_kb;
    }

    // A fragment base for this warp (two m-tiles)
    const uint4* fbase[2];
    #pragma unroll
    for (int mt = 0; mt < 2; ++mt)
        fbase[mt] = g_frag + (((size_t)(b * 16 + otb + mt)) * 9) * 16 * 64 + lane;

    uint4 fh[2][2], fl[2][2];     // [buf][mt]
    // preload (cc=0, t=0)
    #pragma unroll
    for (int mt = 0; mt < 2; ++mt) {
        const uint4* p = fbase[mt];           // frag (t=0, cc=0)
        fh[0][mt] = p[0];
        fl[0][mt] = p[32];
    }

    int stage = 0;
    for (int cc = 0; cc < 16; ++cc) {
        // ---- build slab_t: [spatial][16 ci] fp16 (hi only) ----
        for (int idx = tid; idx < 8 * 180; idx += 256) {
            int cp = idx / 180, s = idx - cp * 180;
            int rr = s / 30, ccx = s - rr * 30;
            int grow = r0 + rr - 1, gcol = ccx - 1;
            float v0 = 0.f, v1 = 0.f;
            if ((unsigned)grow < 28u && (unsigned)gcol < 28u) {
                const float* px = x + (((size_t)(b * 256 + cc * 16 + 2 * cp)) * 28 + grow) * 28 + gcol;
                v0 = px[0];
                v1 = px[784];
            }
            uint32_t hh = ((uint32_t)__half_as_ushort(__float2half_rn(v1)) << 16)
                        |  (uint32_t)__half_as_ushort(__float2half_rn(v0));
            *(uint32_t*)(slabT + s * 48 + cp * 4) = hh;
        }
        __syncthreads();

        #pragma unroll
        for (int t = 0; t < 9; ++t) {
            int cb = stage & 1, nb = cb ^ 1;
            // ---- prefetch A for next tap (or next chunk's t=0) ----
            int ncc = (t == 8) ? cc + 1 : cc;
            int ntp = (t == 8) ? 0 : t + 1;
            if (ncc < 16) {
                #pragma unroll
                for (int mt = 0; mt < 2; ++mt) {
                    const uint4* p = fbase[mt] + ((size_t)ntp * 16 + ncc) * 64;
                    fh[nb][mt] = p[0];
                    fl[nb][mt] = p[32];
                }
            }
            // ---- B fragments ----
            uint32_t dt = (uint32_t)((t / 3) * 30 + (t % 3)) * 48;
            uint32_t bb[7][2];
            #pragma unroll
            for (int np = 0; np < 3; ++np)
                LDSM_X4(bb[2*np][0], bb[2*np][1], bb[2*np+1][0], bb[2*np+1][1],
                        addrB[np] + dt);
            LDSM_X2(bb[6][0], bb[6][1], addrB[3] + dt);

            // ---- MMAs ----
            #pragma unroll
            for (int mt = 0; mt < 2; ++mt) {
                const uint32_t* ah = (const uint32_t*)&fh[cb][mt];
                const uint32_t* al = (const uint32_t*)&fl[cb][mt];
                #pragma unroll
                for (int nt = 0; nt < 7; ++nt) {
                    MMA_F16(d[mt][nt], ah, bb[nt]);
                    MMA_F16(d[mt][nt], al, bb[nt]);
                }
            }
            ++stage;
        }
        __syncthreads();   // all LDSM done before slab_t rewrite
    }

    // ---- epilogue: direct STG.64 ----
    #pragma unroll
    for (int mt = 0; mt < 2; ++mt) {
        int obase = o0 + wm * 32 + mt * 16 + (lane >> 2);
        #pragma unroll
        for (int nt = 0; nt < 7; ++nt) {
            int px = wn * 56 + nt * 8 + (lane & 3) * 2;
            int rl = px / 28, c = px - rl * 28;
            float2* p0 = (float2*)(out + (((size_t)(b * 256 + obase)) * 28 + r0 + rl) * 28 + c);
            float2* p1 = (float2*)(out + (((size_t)(b * 256 + obase + 8)) * 28 + r0 + rl) * 28 + c);
            *p0 = make_float2(d[mt][nt][0], d[mt][nt][1]);
            *p1 = make_float2(d[mt][nt][2], d[mt][nt][3]);
        }
    }
}

// ---------------------------------------------------------------------------
extern "C" void kernel_launch(void* const* d_in, const int* in_sizes, int n_in,
                              void* d_out, int out_size) {
    const float* x     = (const float*)d_in[0];   // [32,256,28,28]
    const float* fc1_w = (const float*)d_in[1];   // [64,256]
    const float* fc2_w = (const float*)d_in[2];   // [1024,64]
    const float* fc2_b = (const float*)d_in[3];   // [1024]
    const float* wexp  = (const float*)d_in[4];   // [4,256,256,3,3]
    float* out = (float*)d_out;                   // [32,256,28,28]

    pool_kernel<<<B_ * CIN_ / 8, 256>>>(x);
    routing_kernel<<<B_, 256>>>(fc1_w, fc2_w, fc2_b);
    aggw_split_kernel<<<dim3(COUT_, 2), 256>>>(wexp);
    repack_frag_kernel<<<dim3(B_, 16), 256>>>();
    conv_mma_kernel<<<dim3(7, 2, B_), 256>>>(x, out);
}

// round 15
// speedup vs baseline: 1.9922x; 1.9922x over previous
#include <cuda_runtime.h>
#include <cuda_fp16.h>
#include <stdint.h>

#define B_    32
#define CIN_  256
#define HW_   784
#define COUT_ 256

// ===========================================================================
// PTX helpers (arch-generic: ldmatrix + mma.sync, valid at sm_103 target)
// ===========================================================================
__device__ __forceinline__ uint32_t smem_to_u32(const void* p) {
    uint32_t a;
    asm("{ .reg .u64 t; cvta.to.shared.u64 t, %1; cvt.u32.u64 %0, t; }" : "=r"(a) : "l"(p));
    return a;
}
#define STS128(r0, r1, r2, r3, smem_addr) \
    asm volatile("st.shared.v4.b32 [%0], {%1, %2, %3, %4};" \
        :: "r"(smem_addr), "r"(r0), "r"(r1), "r"(r2), "r"(r3) : "memory")
#define LDSM_X4(r0, r1, r2, r3, addr) \
    asm volatile("ldmatrix.sync.aligned.m8n8.x4.shared.b16 {%0,%1,%2,%3}, [%4];" \
        : "=r"(r0), "=r"(r1), "=r"(r2), "=r"(r3) : "r"(addr))
#define LDSM_X2(r0, r1, addr) \
    asm volatile("ldmatrix.sync.aligned.m8n8.x2.shared.b16 {%0,%1}, [%2];" \
        : "=r"(r0), "=r"(r1) : "r"(addr))
#define MMA_F16(d, a, bgg) \
    asm volatile("mma.sync.aligned.m16n8k16.row.col.f32.f16.f16.f32 " \
        "{%0,%1,%2,%3}, {%4,%5,%6,%7}, {%8,%9}, {%0,%1,%2,%3};" \
        : "+f"((d)[0]), "+f"((d)[1]), "+f"((d)[2]), "+f"((d)[3]) \
        : "r"((a)[0]), "r"((a)[1]), "r"((a)[2]), "r"((a)[3]), \
          "r"((bgg)[0]), "r"((bgg)[1]))

// ===========================================================================
// Scratch (__device__ globals; allocation-free rule)
// ===========================================================================
__device__ float  g_pooled[B_ * CIN_];
__device__ float  g_prob[B_ * 4 * COUT_];
// Aggregated weights, fp16, layout [b][o][cc(16)][tap(9)][ci(16)]
__device__ __half g_aggw_h[(size_t)B_ * COUT_ * 2304];

// ---------------------------------------------------------------------------
// Kernel 0: pooling.  One warp per (b, channel).
// ---------------------------------------------------------------------------
__global__ void pool_kernel(const float* __restrict__ x) {
    int gw   = blockIdx.x * 8 + (threadIdx.x >> 5);
    int lane = threadIdx.x & 31;
    const float4* xp = (const float4*)(x + (size_t)gw * HW_);
    float s = 0.f;
    for (int i = lane; i < HW_ / 4; i += 32) {
        float4 v = xp[i];
        s += (v.x + v.y) + (v.z + v.w);
    }
    #pragma unroll
    for (int off = 16; off; off >>= 1) s += __shfl_xor_sync(0xffffffffu, s, off);
    if (lane == 0) g_pooled[gw] = s * (1.0f / 784.0f);
}

// ---------------------------------------------------------------------------
// Kernel 1: routing (fc1 + fc2 + softmax).
// ---------------------------------------------------------------------------
__global__ void routing_kernel(const float* __restrict__ fc1_w,
                               const float* __restrict__ fc2_w,
                               const float* __restrict__ fc2_b) {
    int b   = blockIdx.x;
    int tid = threadIdx.x;
    __shared__ float pooled[CIN_];
    __shared__ float hs[64];

    pooled[tid] = g_pooled[b * CIN_ + tid];
    __syncthreads();
    if (tid < 64) {
        const float* wr = fc1_w + (size_t)tid * CIN_;
        float acc = 0.f;
        #pragma unroll 8
        for (int c = 0; c < CIN_; ++c) acc += pooled[c] * wr[c];
        hs[tid] = fmaxf(acc, 0.f);
    }
    __syncthreads();
    int o = tid;
    float y[4];
    #pragma unroll
    for (int k = 0; k < 4; ++k) {
        int m = k * COUT_ + o;
        const float* wr = fc2_w + (size_t)m * 64;
        float acc = fc2_b[m];
        #pragma unroll 8
        for (int j = 0; j < 64; ++j) acc += hs[j] * wr[j];
        y[k] = acc * 0.125f;
    }
    float mx = fmaxf(fmaxf(y[0], y[1]), fmaxf(y[2], y[3]));
    float e[4], se = 0.f;
    #pragma unroll
    for (int k = 0; k < 4; ++k) { e[k] = expf(y[k] - mx); se += e[k]; }
    float inv = 1.0f / se;
    #pragma unroll
    for (int k = 0; k < 4; ++k)
        g_prob[((size_t)b * 4 + k) * COUT_ + o] = e[k] * inv;
}

// ---------------------------------------------------------------------------
// Kernel 2: aggregate -> fp16, layout [b][o][cc][tap][ci].  Grid (o=256, bh=4):
// expert rows staged in smem once, 8 batches per block.
// ---------------------------------------------------------------------------
__global__ void aggw_kernel(const float* __restrict__ weight) {
    __shared__ float s[4][2304];
    int o = blockIdx.x, bh = blockIdx.y, tid = threadIdx.x;

    #pragma unroll
    for (int k = 0; k < 4; ++k) {
        const float* wk = weight + ((size_t)(k * COUT_ + o)) * 2304;
        for (int j = tid; j < 2304; j += 256) s[k][j] = wk[j];
    }
    __syncthreads();

    for (int b = bh * 8; b < bh * 8 + 8; ++b) {
        float p0 = g_prob[((size_t)b * 4 + 0) * COUT_ + o];
        float p1 = g_prob[((size_t)b * 4 + 1) * COUT_ + o];
        float p2 = g_prob[((size_t)b * 4 + 2) * COUT_ + o];
        float p3 = g_prob[((size_t)b * 4 + 3) * COUT_ + o];
        __half2* dst = (__half2*)(g_aggw_h + ((size_t)b * COUT_ + o) * 2304);
        for (int j2 = tid; j2 < 1152; j2 += 256) {
            int j = 2 * j2;
            int cc = j / 144, rem = j - cc * 144;
            int t = rem >> 4, ci = rem & 15;
            int i0 = (cc * 16 + ci) * 9 + t;      // smem [ci][tap]
            float v0 = p0 * s[0][i0]     + p1 * s[1][i0]     + p2 * s[2][i0]     + p3 * s[3][i0];
            float v1 = p0 * s[0][i0 + 9] + p1 * s[1][i0 + 9] + p2 * s[2][i0 + 9] + p3 * s[3][i0 + 9];
            dst[j2] = __floats2half2_rn(v0, v1);
        }
    }
}

// ---------------------------------------------------------------------------
// Kernel 3: conv as single-plane fp16 implicit GEMM on mma.sync.
// CTA: M=128 outs x N=112 px.  8 warps 4(M)x2(N), warp tile 32x56.
// B: x tile stored once per ci-chunk as slab_t[spatial][16 ci] fp16 (48B rows);
//    taps = address offset only.
// A: staged per 3-tap group (one kh row), 128 rows x 112B, double-buffered;
//    build = aligned memcpy (3 LDG.128 + 3 STS.128 per thread).
// 4 barriers per ci-chunk.  14 MMA / warp / tap.
// ---------------------------------------------------------------------------
__global__ __launch_bounds__(256, 3)
void conv_mma_kernel(const float* __restrict__ x, float* __restrict__ out) {
    __shared__ __align__(16) char slabT[180 * 48];        // 8.6 KB
    __shared__ __align__(16) char Abuf[2][128 * 112];     // 28.7 KB

    uint32_t sT = smem_to_u32(slabT);
    uint32_t sA = smem_to_u32(Abuf);

    int tid = threadIdx.x, lane = tid & 31, wid = tid >> 5;
    int b = blockIdx.z, o0 = blockIdx.y * 128, r0 = blockIdx.x * 4;
    int wm = wid & 3, wn = wid >> 2;

    float d[2][7][4];
    #pragma unroll
    for (int mt = 0; mt < 2; ++mt)
        #pragma unroll
        for (int nt = 0; nt < 7; ++nt)
            #pragma unroll
            for (int j = 0; j < 4; ++j) d[mt][nt][j] = 0.f;

    // A ldmatrix lane address components
    int la_row = (lane & 7) + ((lane >> 3) & 1) * 8;
    int la_kb  = (lane >> 4) * 16;
    // B ldmatrix lane addresses (tap adds constant offset dt)
    int lb_row  = (lane & 7) + (lane >> 4) * 8;
    int lb_kb   = ((lane >> 3) & 1) * 16;
    int lb2_row = lane & 7;
    int lb2_kb  = ((lane >> 3) & 1) * 16;
    uint32_t addrB[4];
    #pragma unroll
    for (int np = 0; np < 3; ++np) {
        int n = wn * 56 + np * 16 + lb_row;
        int rl = n / 28, c = n - rl * 28;
        addrB[np] = sT + (uint32_t)(rl * 30 + c) * 48 + lb_kb;
    }
    {
        int n = wn * 56 + 48 + lb2_row;
        int rl = n / 28, c = n - rl * 28;
        addrB[3] = sT + (uint32_t)(rl * 30 + c) * 48 + lb2_kb;
    }

    // A-build mapping: 2 threads per row, 48 B each
    int am = tid >> 1, ahalf = tid & 1;
    const char* asrc_row = (const char*)(g_aggw_h + ((size_t)(b * 256 + o0 + am)) * 2304)
                           + ahalf * 48;
    uint32_t adst = sA + (uint32_t)am * 112 + ahalf * 48;

    for (int cc = 0; cc < 16; ++cc) {
        __syncthreads();   // prev chunk fully consumed (slab + Abuf reuse safe)

        // ---- build slab_t: [spatial][16 ci] fp16 ----
        for (int idx = tid; idx < 8 * 180; idx += 256) {
            int cp = idx / 180, s = idx - cp * 180;
            int rr = s / 30, ccx = s - rr * 30;
            int grow = r0 + rr - 1, gcol = ccx - 1;
            float v0 = 0.f, v1 = 0.f;
            if ((unsigned)grow < 28u && (unsigned)gcol < 28u) {
                const float* px = x + (((size_t)(b * 256 + cc * 16 + 2 * cp)) * 28 + grow) * 28 + gcol;
                v0 = px[0];
                v1 = px[784];
            }
            uint32_t hh = ((uint32_t)__half_as_ushort(__float2half_rn(v1)) << 16)
                        |  (uint32_t)__half_as_ushort(__float2half_rn(v0));
            *(uint32_t*)(slabT + s * 48 + cp * 4) = hh;
        }
        // ---- build A group 0 ----
        {
            const uint4* src = (const uint4*)(asrc_row + (size_t)cc * 288);
            uint4 q0 = src[0], q1 = src[1], q2 = src[2];
            uint32_t dstp = adst;
            STS128(q0.x, q0.y, q0.z, q0.w, dstp);
            STS128(q1.x, q1.y, q1.z, q1.w, dstp + 16);
            STS128(q2.x, q2.y, q2.z, q2.w, dstp + 32);
        }
        __syncthreads();

        #pragma unroll
        for (int g = 0; g < 3; ++g) {
            // ---- build next group into other buffer ----
            if (g < 2) {
                const uint4* src = (const uint4*)(asrc_row + (size_t)cc * 288 + (g + 1) * 96);
                uint4 q0 = src[0], q1 = src[1], q2 = src[2];
                uint32_t dstp = adst + ((g + 1) & 1) * (128 * 112);
                STS128(q0.x, q0.y, q0.z, q0.w, dstp);
                STS128(q1.x, q1.y, q1.z, q1.w, dstp + 16);
                STS128(q2.x, q2.y, q2.z, q2.w, dstp + 32);
            }
            // ---- consume group g: taps (g, tig) ----
            uint32_t sAb = sA + (g & 1) * (128 * 112);
            #pragma unroll
            for (int tig = 0; tig < 3; ++tig) {
                uint32_t a0[4], a1[4];
                uint32_t ra = sAb + (uint32_t)(wm * 32 + la_row) * 112 + tig * 32 + la_kb;
                LDSM_X4(a0[0], a0[1], a0[2], a0[3], ra);
                LDSM_X4(a1[0], a1[1], a1[2], a1[3], ra + 16 * 112);

                uint32_t dt = (uint32_t)(g * 30 + tig) * 48;
                #pragma unroll
                for (int np = 0; np < 3; ++np) {
                    uint32_t b0[2], b1[2];
                    LDSM_X4(b0[0], b0[1], b1[0], b1[1], addrB[np] + dt);
                    MMA_F16(d[0][2 * np],     a0, b0);
                    MMA_F16(d[1][2 * np],     a1, b0);
                    MMA_F16(d[0][2 * np + 1], a0, b1);
                    MMA_F16(d[1][2 * np + 1], a1, b1);
                }
                {
                    uint32_t b0[2];
                    LDSM_X2(b0[0], b0[1], addrB[3] + dt);
                    MMA_F16(d[0][6], a0, b0);
                    MMA_F16(d[1][6], a1, b0);
                }
            }
            __syncthreads();
        }
    }

    // ---- epilogue: direct STG.64 (px pairs never cross 28-col boundary) ----
    #pragma unroll
    for (int mt = 0; mt < 2; ++mt) {
        int obase = o0 + wm * 32 + mt * 16 + (lane >> 2);
        #pragma unroll
        for (int nt = 0; nt < 7; ++nt) {
            int px = wn * 56 + nt * 8 + (lane & 3) * 2;
            int rl = px / 28, c = px - rl * 28;
            float2* p0 = (float2*)(out + (((size_t)(b * 256 + obase)) * 28 + r0 + rl) * 28 + c);
            float2* p1 = (float2*)(out + (((size_t)(b * 256 + obase + 8)) * 28 + r0 + rl) * 28 + c);
            *p0 = make_float2(d[mt][nt][0], d[mt][nt][1]);
            *p1 = make_float2(d[mt][nt][2], d[mt][nt][3]);
        }
    }
}

// ---------------------------------------------------------------------------
extern "C" void kernel_launch(void* const* d_in, const int* in_sizes, int n_in,
                              void* d_out, int out_size) {
    const float* x     = (const float*)d_in[0];   // [32,256,28,28]
    const float* fc1_w = (const float*)d_in[1];   // [64,256]
    const float* fc2_w = (const float*)d_in[2];   // [1024,64]
    const float* fc2_b = (const float*)d_in[3];   // [1024]
    const float* wexp  = (const float*)d_in[4];   // [4,256,256,3,3]
    float* out = (float*)d_out;                   // [32,256,28,28]

    pool_kernel<<<B_ * CIN_ / 8, 256>>>(x);
    routing_kernel<<<B_, 256>>>(fc1_w, fc2_w, fc2_b);
    aggw_kernel<<<dim3(COUT_, 4), 256>>>(wexp);
    conv_mma_kernel<<<dim3(7, 2, B_), 256>>>(x, out);
}